// round 4
// baseline (speedup 1.0000x reference)
#include <cuda_runtime.h>
#include <cuda_bf16.h>
#include <math.h>

#define BB 16
#define CC 256
#define HH 96
#define WW 128
#define HW (HH * WW)          // 12288
#define OUT_H 12
#define OUT_W 16
#define NN (OUT_H * OUT_W)    // 192
#define KH 8
#define KW 8
#define QQ 4
#define HIDDEN 128
#define TAU_INV 10.0f

// ---------------- device scratch (static, zero-initialized) ----------------
__device__ float g_scale[BB * CC];
__device__ float g_da[CC];
__device__ float g_db[CC];
__device__ int   g_viol;                  // bit0: NOT diagonal; bit1: Wb has nonzeros
__device__ unsigned g_acnt;               // analysis-phase arrival counter (scale kernel)
__device__ unsigned g_done;               // fuse-kernel completion counter

__device__ __forceinline__ float sigmoidf_(float z) {
    return __fdividef(1.0f, 1.0f + __expf(-z));
}

// ---------------- kernel 1: wf analysis + (slow-path) scale pipeline ----------------
// grid = 16 blocks x 256 threads. All 16 blocks are trivially co-resident, so the
// spin-barrier between the analysis phase and the flag read cannot deadlock.
__global__ void scale_kernel(const float* __restrict__ x,
                             const float* __restrict__ wf,
                             const float* __restrict__ w1,
                             const float* __restrict__ w2) {
    int b   = blockIdx.x;
    int tid = threadIdx.x;

    // ---- phase 1: structural analysis of wf (all blocks cooperate) ----
    {
        int t = b * 256 + tid;               // 4096 threads
        int viol = 0;
        const float4* wf4 = (const float4*)wf;
        #pragma unroll
        for (int i = 0; i < 8; i++) {
            int g4 = t + i * 4096;           // coalesced float4 index
            float4 v = wf4[g4];
            int g = g4 * 4;                  // element index
            int c = g >> 9;
            int k = g & 511;
            float vv[4] = {v.x, v.y, v.z, v.w};
            #pragma unroll
            for (int j = 0; j < 4; j++) {
                int kk = k + j;
                if ((kk != c) && (kk != CC + c) && vv[j] != 0.0f) viol |= 1;
                if ((kk >= CC) && vv[j] != 0.0f)                  viol |= 2;
            }
        }
        if (b == 0) {                        // capture diagonals
            g_da[tid] = wf[tid * (2 * CC) + tid];
            g_db[tid] = wf[tid * (2 * CC) + CC + tid];
        }
        viol = __syncthreads_or(viol);
        if (tid == 0) {
            if (viol) atomicOr(&g_viol, viol);
            __threadfence();
            atomicAdd(&g_acnt, 1u);
            while (atomicAdd(&g_acnt, 0u) < (unsigned)gridDim.x) { }
        }
        __syncthreads();
    }

    int viol = g_viol;
    if ((viol & 2) == 0) return;             // Wb == 0 -> scale unused (fast path)

    // ---- phase 2 (slow path only): pool -> soft-rank -> soft-quantile -> FCs ----
    __shared__ float s[NN];
    __shared__ float rr[NN];
    __shared__ float2 red[256];
    __shared__ float qv[CC * QQ];
    __shared__ float ts[HIDDEN * QQ];
    const float quant[QQ] = {0.25f, 0.5f, 0.75f, 0.95f};

    for (int c = 0; c < CC; c++) {
        int bc = b * CC + c;
        if (tid < NN) {
            int oh = tid >> 4, ow = tid & 15;
            const float* base = x + (size_t)bc * HW + oh * (KH * WW) + ow * KW;
            float acc = 0.0f;
            #pragma unroll
            for (int r = 0; r < KH; r++) {
                float4 a = *(const float4*)(base + r * WW);
                float4 bb = *(const float4*)(base + r * WW + 4);
                acc += a.x + a.y + a.z + a.w + bb.x + bb.y + bb.z + bb.w;
            }
            s[tid] = acc * (1.0f / 64.0f);
        }
        __syncthreads();
        if (tid < NN) {
            float xi = s[tid];
            float acc = 1.0f;
            #pragma unroll 4
            for (int j = 0; j < NN; j++) acc += sigmoidf_((xi - s[j]) * TAU_INV);
            rr[tid] = acc;
        }
        __syncthreads();
        for (int q = 0; q < QQ; q++) {
            float tq = 1.0f + quant[q] * (float)(NN - 1);
            float e = 0.0f, ex = 0.0f;
            if (tid < NN) {
                e  = __expf(-fabsf(rr[tid] - tq) * TAU_INV);
                ex = e * s[tid];
            }
            red[tid] = make_float2(e, ex);
            __syncthreads();
            for (int st = 128; st >= 1; st >>= 1) {
                if (tid < st) {
                    float2 o = red[tid + st];
                    red[tid].x += o.x;
                    red[tid].y += o.y;
                }
                __syncthreads();
            }
            if (tid == 0) qv[c * QQ + q] = red[0].y / red[0].x;
            __syncthreads();
        }
    }

    for (int idx = tid; idx < HIDDEN * QQ; idx += 256) {
        int h = idx >> 2, q = idx & 3;
        float acc = 0.0f;
        #pragma unroll 4
        for (int c = 0; c < CC; c++) acc += w1[h * CC + c] * qv[c * QQ + q];
        ts[idx] = fmaxf(acc, 0.0f);
    }
    __syncthreads();
    {
        int c = tid;
        float acc = 0.0f;
        #pragma unroll 4
        for (int k = 0; k < HIDDEN * QQ; k++) acc += ts[k] * w2[c * (HIDDEN * QQ) + k];
        g_scale[b * CC + c] = sigmoidf_(acc);
    }
}

// ---------------- kernel 2: fused output ----------------
#define GT_C 64
#define GT_P 64
#define GT_K 16
// grid = 24576 blocks x 256 threads.
// Fast path: 6 segs/plane, 2 float4/thread. General path: 1536 block-slots per
// batch, first 768 carry GEMM tiles.

__global__ void __launch_bounds__(256, 8) fuse_kernel(const float* __restrict__ x,
                                                      const float* __restrict__ wf,
                                                      float* __restrict__ out) {
    __shared__ float Ms[GT_C][GT_K];
    __shared__ float Xs[GT_K][GT_P];

    int viol = g_viol;
    if (!(viol & 1)) {
        // diagonal fast path: out = (da[c] + db[c]*scale[b,c]) * x
        int plane = blockIdx.x / 6;              // b*C + c
        int seg   = blockIdx.x % 6;              // 6 x 512 float4 per plane
        int c = plane & (CC - 1);
        float coeff = g_da[c] + g_db[c] * g_scale[plane];
        size_t off = (size_t)plane * (HW / 4) + seg * 512 + threadIdx.x;
        const float4* src = (const float4*)x + off;
        float4*       dst = (float4*)out      + off;
        float4 v0 = __ldcs(src);
        float4 v1 = __ldcs(src + 256);
        v0.x *= coeff; v0.y *= coeff; v0.z *= coeff; v0.w *= coeff;
        v1.x *= coeff; v1.y *= coeff; v1.z *= coeff; v1.w *= coeff;
        __stcs(dst,       v0);
        __stcs(dst + 256, v1);
    } else {
        // general path: out[b] = (Wa + Wb*diag(scale[b])) @ x[b]
        int b = blockIdx.x / 1536;
        int r = blockIdx.x % 1536;
        if (r < 768) {
            int c0 = (r / 192) * GT_C;
            int p0 = (r % 192) * GT_P;
            int tid = threadIdx.x;
            int ty = tid >> 4, tx = tid & 15;
            float acc[4][4] = {};

            const float* xb = x + (size_t)b * CC * HW;
            const float* sb = g_scale + b * CC;

            for (int k0 = 0; k0 < CC; k0 += GT_K) {
                {
                    int row = tid >> 2;
                    int kk  = (tid & 3) * 4;
                    int cr  = c0 + row;
                    float4 wa = *(const float4*)(wf + cr * (2 * CC) + k0 + kk);
                    float4 wb = *(const float4*)(wf + cr * (2 * CC) + CC + k0 + kk);
                    float4 sc = *(const float4*)(sb + k0 + kk);
                    Ms[row][kk + 0] = wa.x + wb.x * sc.x;
                    Ms[row][kk + 1] = wa.y + wb.y * sc.y;
                    Ms[row][kk + 2] = wa.z + wb.z * sc.z;
                    Ms[row][kk + 3] = wa.w + wb.w * sc.w;
                    int i = tid * 4;
                    int xr = i / GT_P, xc = i % GT_P;
                    float4 u = *(const float4*)(xb + (k0 + xr) * HW + p0 + xc);
                    Xs[xr][xc] = u.x; Xs[xr][xc + 1] = u.y; Xs[xr][xc + 2] = u.z; Xs[xr][xc + 3] = u.w;
                }
                __syncthreads();
                #pragma unroll
                for (int kk = 0; kk < GT_K; kk++) {
                    float a[4], bx[4];
                    #pragma unroll
                    for (int i = 0; i < 4; i++) a[i] = Ms[ty * 4 + i][kk];
                    #pragma unroll
                    for (int j = 0; j < 4; j++) bx[j] = Xs[kk][tx * 4 + j];
                    #pragma unroll
                    for (int i = 0; i < 4; i++)
                        #pragma unroll
                        for (int j = 0; j < 4; j++)
                            acc[i][j] += a[i] * bx[j];
                }
                __syncthreads();
            }
            float* ob = out + (size_t)b * CC * HW;
            #pragma unroll
            for (int i = 0; i < 4; i++) {
                float4 v = make_float4(acc[i][0], acc[i][1], acc[i][2], acc[i][3]);
                *(float4*)(ob + (c0 + ty * 4 + i) * HW + p0 + tx * 4) = v;
            }
        }
    }

    // last finishing block resets per-call state for the next graph replay
    if (threadIdx.x == 0) {
        if (atomicAdd(&g_done, 1u) == (unsigned)(gridDim.x - 1)) {
            g_viol = 0;
            g_acnt = 0;
            g_done = 0;
        }
    }
}

// ---------------- launch ----------------
extern "C" void kernel_launch(void* const* d_in, const int* in_sizes, int n_in,
                              void* d_out, int out_size) {
    const float* x  = (const float*)d_in[0];
    const float* w1 = (const float*)d_in[1];
    const float* w2 = (const float*)d_in[2];
    const float* wf = (const float*)d_in[3];
    float* out = (float*)d_out;

    scale_kernel<<<BB, 256>>>(x, wf, w1, w2);
    fuse_kernel<<<BB * CC * 6, 256>>>(x, wf, out);
}